// round 15
// baseline (speedup 1.0000x reference)
#include <cuda_runtime.h>
#include <cstdint>

// Problem constants (fixed by the dataset)
#define NMAX    500000
#define EMAX    2000000
#define EMB     32
#define IN_DIM  65
#define TB      256
#define STRIDE  32            // ELL width; P(indegree > 32) ~ 1e-15 for this input
#define OVFCAP  8192
#define NBINS   33            // degree bins 0..32 (32 = "heavy")

// Scratch (allocation-free rule: __device__ globals).
// INVARIANT: g_cnt, g_hist, g_binfill, g_packdone are zero at kernel_launch
// entry (zero-init at load; each launch self-resets them) -> deterministic.
__device__ int g_novf;
__device__ unsigned g_packdone;                          // last-block counter (self-resets)
__device__ __align__(128) int  g_cnt[NMAX];              // indegree (reset by aggpool)
__device__ __align__(128) int  g_ell[(size_t)NMAX * STRIDE]; // ELL: src ids
__device__ __align__(128) int2 g_ovf[OVFCAP];            // overflow {dst, src}
__device__ __align__(128) unsigned short g_packed16[NMAX]; // (x<<6) | min(cnt,63)
__device__ __align__(128) int  g_perm[NMAX];             // nodes sorted by degree bin
__device__ __align__(128) int  g_hist[64];               // bin histogram (reset by pack)
__device__ __align__(128) int  g_binbase[64];            // exclusive scan of hist
__device__ __align__(128) int  g_binfill[64];            // bump cursors (reset by aggpool)

// ---------------------------------------------------------------------------
// K1: tiny init: out[g] = b_out[0], reset overflow counter
// ---------------------------------------------------------------------------
__global__ void k_init(float* __restrict__ out, const float* __restrict__ b_out,
                       int G) {
    int i = blockIdx.x * blockDim.x + threadIdx.x;
    if (i < G) out[i] = b_out[0];
    if (i == 0) g_novf = 0;
}

// ---------------------------------------------------------------------------
// K2: ONE pass over edges: count indegree AND scatter src into ELL slot.
//     8 edges/thread for MLP (kernel is latency-bound).
// ---------------------------------------------------------------------------
__device__ __forceinline__ void fill_one(int d, int s) {
    int r = atomicAdd(&g_cnt[d], 1);
    if (r < STRIDE) {
        g_ell[(size_t)d * STRIDE + r] = s;
    } else {
        int o = atomicAdd(&g_novf, 1);
        if (o < OVFCAP) g_ovf[o] = make_int2(d, s);
    }
}

__global__ void k_degfill(const int* __restrict__ src, const int* __restrict__ dst,
                          int E) {
    int t = blockIdx.x * blockDim.x + threadIdx.x;
    int e = t * 8;
    if (e + 7 < E) {
        const int4* pd = reinterpret_cast<const int4*>(dst + e);
        const int4* ps = reinterpret_cast<const int4*>(src + e);
        int4 d0 = pd[0], d1 = pd[1];
        int4 s0 = ps[0], s1 = ps[1];
        fill_one(d0.x, s0.x); fill_one(d0.y, s0.y);
        fill_one(d0.z, s0.z); fill_one(d0.w, s0.w);
        fill_one(d1.x, s1.x); fill_one(d1.y, s1.y);
        fill_one(d1.z, s1.z); fill_one(d1.w, s1.w);
    } else {
        for (int k = e; k < E; k++) fill_one(dst[k], src[k]);
    }
}

// ---------------------------------------------------------------------------
// K3: packed16[i] = (x<<6) | min(cnt,63); degree-bin histogram;
//     LAST BLOCK scans the 33 bins into g_binbase, then re-zeros g_hist.
// ---------------------------------------------------------------------------
__global__ void k_pack(const int* __restrict__ x, int N) {
    __shared__ int sh[NBINS];
    __shared__ unsigned s_isLast;
    __shared__ int w0tot;
    if (threadIdx.x < NBINS) sh[threadIdx.x] = 0;
    __syncthreads();
    int i = blockIdx.x * blockDim.x + threadIdx.x;
    if (i < N) {
        int c = g_cnt[i];
        int c6 = c < 63 ? c : 63;
        g_packed16[i] = (unsigned short)(c6 | (x[i] << 6));
        int bin = c < STRIDE ? c : STRIDE;
        atomicAdd(&sh[bin], 1);
    }
    __syncthreads();
    if (threadIdx.x < NBINS && sh[threadIdx.x] > 0)
        atomicAdd(&g_hist[threadIdx.x], sh[threadIdx.x]);

    // last-block-done: final block scans histogram -> g_binbase, zeros g_hist
    __threadfence();
    __syncthreads();
    if (threadIdx.x == 0)
        s_isLast = (atomicAdd(&g_packdone, 1u) == gridDim.x - 1u) ? 1u : 0u;
    __syncthreads();
    if (s_isLast) {
        int t = threadIdx.x;
        int v = 0, incl = 0;
        if (t < 32) {
            v = g_hist[t];
            incl = v;
#pragma unroll
            for (int o = 1; o < 32; o <<= 1) {
                int u = __shfl_up_sync(0xffffffffu, incl, o);
                if (t >= o) incl += u;
            }
            if (t == 31) w0tot = incl;
        }
        __syncthreads();                       // cross-warp: w0tot visible
        if (t < 32) g_binbase[t] = incl - v;
        if (t == 32) g_binbase[32] = w0tot;    // bins 0..31 sum
        if (t < NBINS) g_hist[t] = 0;          // self-reset for next launch
        if (t == 0) g_packdone = 0u;           // self-reset
    }
}

// ---------------------------------------------------------------------------
// K4: scatter node ids into degree-sorted order; 4 nodes/thread.
// ---------------------------------------------------------------------------
__global__ void k_scatter(int N) {
    __shared__ int lcnt[NBINS];
    __shared__ int lbase[NBINS];
    if (threadIdx.x < NBINS) lcnt[threadIdx.x] = 0;
    __syncthreads();
    int base = (blockIdx.x * blockDim.x + threadIdx.x) * 4;
    int bins[4], lrank[4];
#pragma unroll
    for (int j = 0; j < 4; j++) {
        int i = base + j;
        if (i < N) {
            int c = g_packed16[i] & 63;
            int b = c < STRIDE ? c : STRIDE;
            bins[j]  = b;
            lrank[j] = atomicAdd(&lcnt[b], 1);
        }
    }
    __syncthreads();
    if (threadIdx.x < NBINS && lcnt[threadIdx.x] > 0)
        lbase[threadIdx.x] = atomicAdd(&g_binfill[threadIdx.x], lcnt[threadIdx.x]);
    __syncthreads();
#pragma unroll
    for (int j = 0; j < 4; j++) {
        int i = base + j;
        if (i < N)
            g_perm[g_binbase[bins[j]] + lbase[bins[j]] + lrank[j]] = i;
    }
}

// ---------------------------------------------------------------------------
// K5: 4 lanes per node (degree-sorted), 8 EMB-columns per lane.
//     Per edge: 2B payload gather + 64-entry dinv LUT + 2x LDS.128.
//     Also self-resets g_cnt and g_binfill for the next launch.
// ---------------------------------------------------------------------------
__device__ __forceinline__ float tanha(float v) {
    float r;
    asm("tanh.approx.f32 %0, %1;" : "=f"(r) : "f"(v));
    return r;
}

#define WPITCH4 9   // float4 pitch per W row (36 floats)

__global__ void __launch_bounds__(TB)
k_aggpool(const int* __restrict__ batch,
          const float* __restrict__ W,
          const float* __restrict__ b_conv,
          const float* __restrict__ W_out,
          float* __restrict__ out, int N) {
    __shared__ float4 sW4[IN_DIM * WPITCH4];
    __shared__ float sb[EMB];
    __shared__ float so[EMB];
    __shared__ float sLUT[64];
    {
        float* sWf = reinterpret_cast<float*>(sW4);
        for (int t = threadIdx.x; t < IN_DIM * EMB; t += blockDim.x) {
            int r = t / EMB, cc = t % EMB;
            sWf[r * (WPITCH4 * 4) + cc] = W[t];
        }
    }
    if (threadIdx.x < EMB) {
        sb[threadIdx.x] = b_conv[threadIdx.x];
        so[threadIdx.x] = W_out[threadIdx.x];
    }
    if (threadIdx.x < 64)
        sLUT[threadIdx.x] = rsqrtf(1.0f + (float)threadIdx.x);
    if (blockIdx.x == 0 && threadIdx.x < 64)
        g_binfill[threadIdx.x] = 0;            // self-reset (consumed by scatter)
    __syncthreads();

    int t   = blockIdx.x * TB + threadIdx.x;
    int idx = t >> 2;           // position in degree-sorted order
    int sub = t & 3;            // column group: columns [8*sub, 8*sub+8)
    if (idx >= N) return;
    int node = g_perm[idx];     // 4 lanes same address -> broadcast

    unsigned up = g_packed16[node];
    int cnt16 = up & 63;
    int xi    = up >> 6;
    float dinv = (cnt16 < 63) ? sLUT[cnt16]
                              : rsqrtf(1.0f + (float)g_cnt[node]);
    int   f0   = sub * 2;       // float4 index of this lane's first quad
    const int* row_ell = g_ell + (size_t)node * STRIDE;

    float4 acc0, acc1;
    {
        const float4* row = &sW4[xi * WPITCH4 + f0];
        float4 w0 = row[0], w1 = row[1];
        acc0 = make_float4(dinv * w0.x, dinv * w0.y, dinv * w0.z, dinv * w0.w);
        acc1 = make_float4(dinv * w1.x, dinv * w1.y, dinv * w1.z, dinv * w1.w);
    }

    int m = cnt16 <= STRIDE ? cnt16 : STRIDE;
    for (int k = 0; k < m; k += 4) {
        int4 q = *reinterpret_cast<const int4*>(row_ell + k);  // broadcast
        int lim = m - k;
        {
            unsigned u = g_packed16[q.x];
            int c = u & 63;
            float ds = (c < 63) ? sLUT[c] : rsqrtf(1.0f + (float)g_cnt[q.x]);
            const float4* r = &sW4[(u >> 6) * WPITCH4 + f0];
            float4 a0 = r[0], a1 = r[1];
            acc0.x += ds * a0.x; acc0.y += ds * a0.y; acc0.z += ds * a0.z; acc0.w += ds * a0.w;
            acc1.x += ds * a1.x; acc1.y += ds * a1.y; acc1.z += ds * a1.z; acc1.w += ds * a1.w;
        }
        if (lim > 1) {
            unsigned u = g_packed16[q.y];
            int c = u & 63;
            float ds = (c < 63) ? sLUT[c] : rsqrtf(1.0f + (float)g_cnt[q.y]);
            const float4* r = &sW4[(u >> 6) * WPITCH4 + f0];
            float4 a0 = r[0], a1 = r[1];
            acc0.x += ds * a0.x; acc0.y += ds * a0.y; acc0.z += ds * a0.z; acc0.w += ds * a0.w;
            acc1.x += ds * a1.x; acc1.y += ds * a1.y; acc1.z += ds * a1.z; acc1.w += ds * a1.w;
        }
        if (lim > 2) {
            unsigned u = g_packed16[q.z];
            int c = u & 63;
            float ds = (c < 63) ? sLUT[c] : rsqrtf(1.0f + (float)g_cnt[q.z]);
            const float4* r = &sW4[(u >> 6) * WPITCH4 + f0];
            float4 a0 = r[0], a1 = r[1];
            acc0.x += ds * a0.x; acc0.y += ds * a0.y; acc0.z += ds * a0.z; acc0.w += ds * a0.w;
            acc1.x += ds * a1.x; acc1.y += ds * a1.y; acc1.z += ds * a1.z; acc1.w += ds * a1.w;
        }
        if (lim > 3) {
            unsigned u = g_packed16[q.w];
            int c = u & 63;
            float ds = (c < 63) ? sLUT[c] : rsqrtf(1.0f + (float)g_cnt[q.w]);
            const float4* r = &sW4[(u >> 6) * WPITCH4 + f0];
            float4 a0 = r[0], a1 = r[1];
            acc0.x += ds * a0.x; acc0.y += ds * a0.y; acc0.z += ds * a0.z; acc0.w += ds * a0.w;
            acc1.x += ds * a1.x; acc1.y += ds * a1.y; acc1.z += ds * a1.z; acc1.w += ds * a1.w;
        }
    }

    // Heavy-node path (never taken on this input; correctness fallback).
    if (cnt16 > STRIDE) {
        int novf = g_novf;
        if (novf > OVFCAP) novf = OVFCAP;
        for (int j2 = 0; j2 < novf; j2++) {
            int2 ov = g_ovf[j2];
            if (ov.x == node) {
                unsigned u = g_packed16[ov.y];
                int c = u & 63;
                float ds = (c < 63) ? sLUT[c] : rsqrtf(1.0f + (float)g_cnt[ov.y]);
                const float4* rr = &sW4[(u >> 6) * WPITCH4 + f0];
                float4 a0 = rr[0], a1 = rr[1];
                acc0.x += ds * a0.x; acc0.y += ds * a0.y; acc0.z += ds * a0.z; acc0.w += ds * a0.w;
                acc1.x += ds * a1.x; acc1.y += ds * a1.y; acc1.z += ds * a1.z; acc1.w += ds * a1.w;
            }
        }
    }

    int col0 = sub * 8;
    float res = 0.f;
    res += tanha(acc0.x * dinv + sb[col0 + 0]) * so[col0 + 0];
    res += tanha(acc0.y * dinv + sb[col0 + 1]) * so[col0 + 1];
    res += tanha(acc0.z * dinv + sb[col0 + 2]) * so[col0 + 2];
    res += tanha(acc0.w * dinv + sb[col0 + 3]) * so[col0 + 3];
    res += tanha(acc1.x * dinv + sb[col0 + 4]) * so[col0 + 4];
    res += tanha(acc1.y * dinv + sb[col0 + 5]) * so[col0 + 5];
    res += tanha(acc1.z * dinv + sb[col0 + 6]) * so[col0 + 6];
    res += tanha(acc1.w * dinv + sb[col0 + 7]) * so[col0 + 7];

    // reduce across the 4 lanes of this node
    res += __shfl_xor_sync(0xffffffffu, res, 1);
    res += __shfl_xor_sync(0xffffffffu, res, 2);
    if (sub == 0) {
        atomicAdd(&out[batch[node]], res);
        g_cnt[node] = 0;                       // self-reset (each node exactly once)
    }
}

// ---------------------------------------------------------------------------
// Launch
// Inputs: 0:x[N] i32, 1:edge_index[2E] i32, 2:batch[N] i32,
//         3:W[65*32] f32, 4:b_conv[32] f32, 5:W_out[32] f32, 6:b_out[1] f32
// Output: out[G] f32
// ---------------------------------------------------------------------------
extern "C" void kernel_launch(void* const* d_in, const int* in_sizes, int n_in,
                              void* d_out, int out_size) {
    const int*   x     = (const int*)d_in[0];
    const int*   eidx  = (const int*)d_in[1];
    const int*   batch = (const int*)d_in[2];
    const float* W     = (const float*)d_in[3];
    const float* bconv = (const float*)d_in[4];
    const float* Wout  = (const float*)d_in[5];
    const float* bout  = (const float*)d_in[6];
    float* out = (float*)d_out;

    int N = in_sizes[0];
    int E = in_sizes[1] / 2;
    int G = out_size;

    const int* src = eidx;
    const int* dst = eidx + E;

    int nbE8 = ((E + 7) / 8 + TB - 1) / TB;
    int nbN  = (N + TB - 1) / TB;
    int nbN4 = (int)(((size_t)N * 4 + TB - 1) / TB);
    int nbS  = ((N + 3) / 4 + TB - 1) / TB;

    k_init   <<<(G + TB - 1) / TB, TB>>>(out, bout, G);
    k_degfill<<<nbE8, TB>>>(src, dst, E);
    k_pack   <<<nbN, TB>>>(x, N);
    k_scatter<<<nbS, TB>>>(N);
    k_aggpool<<<nbN4, TB>>>(batch, W, bconv, Wout, out, N);
}

// round 16
// speedup vs baseline: 1.0674x; 1.0674x over previous
#include <cuda_runtime.h>
#include <cstdint>

// Problem constants (fixed by the dataset)
#define NMAX    500000
#define EMAX    2000000
#define EMB     32
#define IN_DIM  65
#define TB      256
#define STRIDE  32            // ELL width; P(indegree > 32) ~ 1e-15 for this input
#define OVFCAP  8192

// Scratch (allocation-free rule: __device__ globals)
__device__ int g_novf;
__device__ __align__(128) int  g_cnt[NMAX];              // indegree (excl. self-loop)
__device__ __align__(128) int  g_ell[(size_t)NMAX * STRIDE]; // ELL: src ids
__device__ __align__(128) int2 g_ovf[OVFCAP];            // overflow {dst, src}
__device__ __align__(128) unsigned short g_packed16[NMAX]; // (x<<6) | min(cnt,63)

// ---------------------------------------------------------------------------
// K1: zero counts, out[g] = b_out[0]
// ---------------------------------------------------------------------------
__global__ void k_init(float* __restrict__ out, const float* __restrict__ b_out,
                       int N, int G) {
    int i = blockIdx.x * blockDim.x + threadIdx.x;
    if (i < N) g_cnt[i] = 0;
    if (i < G) out[i] = b_out[0];
    if (i == 0) g_novf = 0;
}

// ---------------------------------------------------------------------------
// K2: ONE pass over edges: count indegree AND scatter src into ELL slot.
// ---------------------------------------------------------------------------
__device__ __forceinline__ void fill_one(int d, int s) {
    int r = atomicAdd(&g_cnt[d], 1);
    if (r < STRIDE) {
        g_ell[(size_t)d * STRIDE + r] = s;
    } else {
        int o = atomicAdd(&g_novf, 1);
        if (o < OVFCAP) g_ovf[o] = make_int2(d, s);
    }
}

__global__ void k_degfill(const int* __restrict__ src, const int* __restrict__ dst,
                          int E) {
    int t = blockIdx.x * blockDim.x + threadIdx.x;
    int e = t * 4;
    if (e + 3 < E) {
        int4 d4 = *reinterpret_cast<const int4*>(dst + e);
        int4 s4 = *reinterpret_cast<const int4*>(src + e);
        fill_one(d4.x, s4.x);
        fill_one(d4.y, s4.y);
        fill_one(d4.z, s4.z);
        fill_one(d4.w, s4.w);
    } else {
        for (int k = e; k < E; k++) fill_one(dst[k], src[k]);
    }
}

// ---------------------------------------------------------------------------
// K3: packed16[i] = (x<<6) | min(cnt,63)
// ---------------------------------------------------------------------------
__global__ void k_pack(const int* __restrict__ x, int N) {
    int i = blockIdx.x * blockDim.x + threadIdx.x;
    if (i < N) {
        int c = g_cnt[i];
        int c6 = c < 63 ? c : 63;
        g_packed16[i] = (unsigned short)(c6 | (x[i] << 6));
    }
}

// ---------------------------------------------------------------------------
// K4: 4 lanes per node, 8 EMB-columns per lane, float4 LDS (WPITCH4=9).
//     Per edge: ONE broadcast int4 ELL read per 4 edges + 2B payload gather
//     (1 MB table -> L2-resident, strong L1 hit odds) + dinv via smem LUT.
// ---------------------------------------------------------------------------
__device__ __forceinline__ float tanha(float v) {
    float r;
    asm("tanh.approx.f32 %0, %1;" : "=f"(r) : "f"(v));
    return r;
}

#define WPITCH4 9   // float4 pitch per W row (36 floats)

__global__ void __launch_bounds__(TB)
k_aggpool(const int* __restrict__ batch,
          const float* __restrict__ W,
          const float* __restrict__ b_conv,
          const float* __restrict__ W_out,
          float* __restrict__ out, int N) {
    __shared__ float4 sW4[IN_DIM * WPITCH4];
    __shared__ float sb[EMB];
    __shared__ float so[EMB];
    __shared__ float sLUT[64];
    {
        float* sWf = reinterpret_cast<float*>(sW4);
        for (int t = threadIdx.x; t < IN_DIM * EMB; t += blockDim.x) {
            int r = t / EMB, cc = t % EMB;
            sWf[r * (WPITCH4 * 4) + cc] = W[t];
        }
    }
    if (threadIdx.x < EMB) {
        sb[threadIdx.x] = b_conv[threadIdx.x];
        so[threadIdx.x] = W_out[threadIdx.x];
    }
    if (threadIdx.x < 64)
        sLUT[threadIdx.x] = rsqrtf(1.0f + (float)threadIdx.x);
    __syncthreads();

    int t    = blockIdx.x * TB + threadIdx.x;
    int node = t >> 2;          // 4 lanes per node
    int sub  = t & 3;           // column group: columns [8*sub, 8*sub+8)
    if (node >= N) return;

    unsigned up = g_packed16[node];   // broadcast across the 4 lanes
    int cnt16 = up & 63;
    int xi    = up >> 6;
    float dinv = (cnt16 < 63) ? sLUT[cnt16]
                              : rsqrtf(1.0f + (float)g_cnt[node]);
    int   f0   = sub * 2;       // float4 index of this lane's first quad
    const int* row_ell = g_ell + (size_t)node * STRIDE;

    float4 acc0, acc1;
    {
        const float4* row = &sW4[xi * WPITCH4 + f0];
        float4 w0 = row[0], w1 = row[1];
        acc0 = make_float4(dinv * w0.x, dinv * w0.y, dinv * w0.z, dinv * w0.w);
        acc1 = make_float4(dinv * w1.x, dinv * w1.y, dinv * w1.z, dinv * w1.w);
    }

    int m = cnt16 <= STRIDE ? cnt16 : STRIDE;
    for (int k = 0; k < m; k += 4) {
        int4 q = *reinterpret_cast<const int4*>(row_ell + k);  // broadcast
        int lim = m - k;
        {
            unsigned u = g_packed16[q.x];
            int c = u & 63;
            float ds = (c < 63) ? sLUT[c] : rsqrtf(1.0f + (float)g_cnt[q.x]);
            const float4* r = &sW4[(u >> 6) * WPITCH4 + f0];
            float4 a0 = r[0], a1 = r[1];
            acc0.x += ds * a0.x; acc0.y += ds * a0.y; acc0.z += ds * a0.z; acc0.w += ds * a0.w;
            acc1.x += ds * a1.x; acc1.y += ds * a1.y; acc1.z += ds * a1.z; acc1.w += ds * a1.w;
        }
        if (lim > 1) {
            unsigned u = g_packed16[q.y];
            int c = u & 63;
            float ds = (c < 63) ? sLUT[c] : rsqrtf(1.0f + (float)g_cnt[q.y]);
            const float4* r = &sW4[(u >> 6) * WPITCH4 + f0];
            float4 a0 = r[0], a1 = r[1];
            acc0.x += ds * a0.x; acc0.y += ds * a0.y; acc0.z += ds * a0.z; acc0.w += ds * a0.w;
            acc1.x += ds * a1.x; acc1.y += ds * a1.y; acc1.z += ds * a1.z; acc1.w += ds * a1.w;
        }
        if (lim > 2) {
            unsigned u = g_packed16[q.z];
            int c = u & 63;
            float ds = (c < 63) ? sLUT[c] : rsqrtf(1.0f + (float)g_cnt[q.z]);
            const float4* r = &sW4[(u >> 6) * WPITCH4 + f0];
            float4 a0 = r[0], a1 = r[1];
            acc0.x += ds * a0.x; acc0.y += ds * a0.y; acc0.z += ds * a0.z; acc0.w += ds * a0.w;
            acc1.x += ds * a1.x; acc1.y += ds * a1.y; acc1.z += ds * a1.z; acc1.w += ds * a1.w;
        }
        if (lim > 3) {
            unsigned u = g_packed16[q.w];
            int c = u & 63;
            float ds = (c < 63) ? sLUT[c] : rsqrtf(1.0f + (float)g_cnt[q.w]);
            const float4* r = &sW4[(u >> 6) * WPITCH4 + f0];
            float4 a0 = r[0], a1 = r[1];
            acc0.x += ds * a0.x; acc0.y += ds * a0.y; acc0.z += ds * a0.z; acc0.w += ds * a0.w;
            acc1.x += ds * a1.x; acc1.y += ds * a1.y; acc1.z += ds * a1.z; acc1.w += ds * a1.w;
        }
    }

    // Heavy-node path (never taken on this input; correctness fallback).
    if (cnt16 > STRIDE) {
        int novf = g_novf;
        if (novf > OVFCAP) novf = OVFCAP;
        for (int j2 = 0; j2 < novf; j2++) {
            int2 ov = g_ovf[j2];
            if (ov.x == node) {
                unsigned u = g_packed16[ov.y];
                int c = u & 63;
                float ds = (c < 63) ? sLUT[c] : rsqrtf(1.0f + (float)g_cnt[ov.y]);
                const float4* rr = &sW4[(u >> 6) * WPITCH4 + f0];
                float4 a0 = rr[0], a1 = rr[1];
                acc0.x += ds * a0.x; acc0.y += ds * a0.y; acc0.z += ds * a0.z; acc0.w += ds * a0.w;
                acc1.x += ds * a1.x; acc1.y += ds * a1.y; acc1.z += ds * a1.z; acc1.w += ds * a1.w;
            }
        }
    }

    int col0 = sub * 8;
    float res = 0.f;
    res += tanha(acc0.x * dinv + sb[col0 + 0]) * so[col0 + 0];
    res += tanha(acc0.y * dinv + sb[col0 + 1]) * so[col0 + 1];
    res += tanha(acc0.z * dinv + sb[col0 + 2]) * so[col0 + 2];
    res += tanha(acc0.w * dinv + sb[col0 + 3]) * so[col0 + 3];
    res += tanha(acc1.x * dinv + sb[col0 + 4]) * so[col0 + 4];
    res += tanha(acc1.y * dinv + sb[col0 + 5]) * so[col0 + 5];
    res += tanha(acc1.z * dinv + sb[col0 + 6]) * so[col0 + 6];
    res += tanha(acc1.w * dinv + sb[col0 + 7]) * so[col0 + 7];

    // reduce across the 4 lanes of this node
    res += __shfl_xor_sync(0xffffffffu, res, 1);
    res += __shfl_xor_sync(0xffffffffu, res, 2);
    if (sub == 0) atomicAdd(&out[batch[node]], res);
}

// ---------------------------------------------------------------------------
// Launch
// Inputs: 0:x[N] i32, 1:edge_index[2E] i32, 2:batch[N] i32,
//         3:W[65*32] f32, 4:b_conv[32] f32, 5:W_out[32] f32, 6:b_out[1] f32
// Output: out[G] f32
// ---------------------------------------------------------------------------
extern "C" void kernel_launch(void* const* d_in, const int* in_sizes, int n_in,
                              void* d_out, int out_size) {
    const int*   x     = (const int*)d_in[0];
    const int*   eidx  = (const int*)d_in[1];
    const int*   batch = (const int*)d_in[2];
    const float* W     = (const float*)d_in[3];
    const float* bconv = (const float*)d_in[4];
    const float* Wout  = (const float*)d_in[5];
    const float* bout  = (const float*)d_in[6];
    float* out = (float*)d_out;

    int N = in_sizes[0];
    int E = in_sizes[1] / 2;
    int G = out_size;

    const int* src = eidx;
    const int* dst = eidx + E;

    int initN = N > G ? N : G;
    int nbE4  = ((E + 3) / 4 + TB - 1) / TB;
    int nbN   = (N + TB - 1) / TB;
    int nbN4  = (int)(((size_t)N * 4 + TB - 1) / TB);

    k_init   <<<(initN + TB - 1) / TB, TB>>>(out, bout, N, G);
    k_degfill<<<nbE4, TB>>>(src, dst, E);
    k_pack   <<<nbN, TB>>>(x, N);
    k_aggpool<<<nbN4, TB>>>(batch, W, bconv, Wout, out, N);
}